// round 7
// baseline (speedup 1.0000x reference)
#include <cuda_runtime.h>
#include <cstdint>

// FWHT over rows of length 4096: H4096 = H2^{⊗12}.
// 64 threads/CTA, 64 elements/thread held as 16 float4 registers.
// Rounds (bit groups): A = {0,1,8,9,10,11} (register, from coalesced loads),
//                      B = {2,3,4,5}, C = {6,7}.  Two smem exchanges.
// All global/shared accesses are 128-bit. XOR swizzle on address bits {4,5,6}
//   f4=i4^i7, f5=i5^i2^i8, f6=i6^i3^i8
// makes every LDS.128/STS.128 pattern 8-distinct per lane-quarter (bank
// conflict free); bits 0..3 untouched -> 16B alignment preserved.

#define FWHT_N 4096
#define FWHT_THREADS 64

__device__ __forceinline__ int fwht_swz(int i) {
    int s4 = (i >> 7) & 1;
    int s5 = ((i >> 2) ^ (i >> 8)) & 1;
    int s6 = ((i >> 3) ^ (i >> 8)) & 1;
    return i ^ (s4 << 4) ^ (s5 << 5) ^ (s6 << 6);
}

// H16 butterfly across the 16 float4 registers (componentwise).
__device__ __forceinline__ void fwht_h16_vec(float4* v) {
#pragma unroll
    for (int h = 1; h < 16; h <<= 1) {
#pragma unroll
        for (int s = 0; s < 16; s += 2 * h) {
#pragma unroll
            for (int k = 0; k < h; k++) {
                float4 a = v[s + k];
                float4 b = v[s + k + h];
                v[s + k]     = make_float4(a.x + b.x, a.y + b.y, a.z + b.z, a.w + b.w);
                v[s + k + h] = make_float4(a.x - b.x, a.y - b.y, a.z - b.z, a.w - b.w);
            }
        }
    }
}

// H4 butterfly inside one float4 (element bits {0,1}).
__device__ __forceinline__ float4 fwht_h4_in(float4 a) {
    float x0 = a.x + a.y, x1 = a.x - a.y;
    float x2 = a.z + a.w, x3 = a.z - a.w;
    return make_float4(x0 + x2, x1 + x3, x0 - x2, x1 - x3);
}

__global__ void __launch_bounds__(FWHT_THREADS)
fwht4096_kernel(const float* __restrict__ x,
                const float* __restrict__ scale,
                float* __restrict__ out)
{
    __shared__ float S[FWHT_N];

    const int row = blockIdx.x;
    const int t   = threadIdx.x;          // 0..63

    const float4* xr = reinterpret_cast<const float4*>(x) + (size_t)row * (FWHT_N / 4);
    float4*       or4 = reinterpret_cast<float4*>(out)    + (size_t)row * (FWHT_N / 4);

    float4 v[16];

    // ---- load: v[q] = x[row, 256q + 4t .. +3]  (16 coalesced LDG.128) ----
    // register bits: q -> elem bits {8..11}, float4 lane -> bits {0,1}
#pragma unroll
    for (int q = 0; q < 16; q++)
        v[q] = __ldcs(&xr[64 * q + t]);

    // ---- round A: bits {8..11} across regs, bits {0,1} inside float4 ----
    fwht_h16_vec(v);
#pragma unroll
    for (int q = 0; q < 16; q++)
        v[q] = fwht_h4_in(v[q]);

    // ---- exchange 1: write i = 4t + 256q (swizzled STS.128) ----
#pragma unroll
    for (int q = 0; q < 16; q++)
        *reinterpret_cast<float4*>(&S[fwht_swz(4 * t + 256 * q)]) = v[q];
    __syncthreads();

    // ---- round B: bits {2..5}. regs span elem bits {0..5}: i = 64t + 4q ----
#pragma unroll
    for (int q = 0; q < 16; q++)
        v[q] = *reinterpret_cast<const float4*>(&S[fwht_swz(64 * t + 4 * q)]);

    fwht_h16_vec(v);   // butterfly over q = elem bits {2..5}

#pragma unroll
    for (int q = 0; q < 16; q++)
        *reinterpret_cast<float4*>(&S[fwht_swz(64 * t + 4 * q)]) = v[q];
    __syncthreads();

    // ---- round C: bits {6,7}. thread owns bits {4,5}=t&3, {8..11}=t>>2 ----
    {
        const int base = ((t & 3) << 4) | ((t >> 2) << 8);
#pragma unroll
        for (int b = 0; b < 4; b++)
#pragma unroll
            for (int q = 0; q < 4; q++)
                v[b * 4 + q] = *reinterpret_cast<const float4*>(
                    &S[fwht_swz(base | (q << 2) | (b << 6))]);

        // H4 across b groups (elem bits {6,7})
#pragma unroll
        for (int h = 1; h < 4; h <<= 1) {
#pragma unroll
            for (int s = 0; s < 4; s += 2 * h) {
#pragma unroll
                for (int k = 0; k < h; k++) {
#pragma unroll
                    for (int q = 0; q < 4; q++) {
                        float4 a = v[(s + k) * 4 + q];
                        float4 b2 = v[(s + k + h) * 4 + q];
                        v[(s + k) * 4 + q] =
                            make_float4(a.x + b2.x, a.y + b2.y, a.z + b2.z, a.w + b2.w);
                        v[(s + k + h) * 4 + q] =
                            make_float4(a.x - b2.x, a.y - b2.y, a.z - b2.z, a.w - b2.w);
                    }
                }
            }
        }

        const float sc = *scale;
        const int obase = base >> 2;   // float4 index: bits {2,3}=t&3, {6..9}=t>>2
#pragma unroll
        for (int b = 0; b < 4; b++)
#pragma unroll
            for (int q = 0; q < 4; q++) {
                float4 a = v[b * 4 + q];
                __stcs(&or4[obase | q | (b << 4)],
                       make_float4(a.x * sc, a.y * sc, a.z * sc, a.w * sc));
            }
    }
}

extern "C" void kernel_launch(void* const* d_in, const int* in_sizes, int n_in,
                              void* d_out, int out_size)
{
    const float* x     = (const float*)d_in[0];
    const float* scale = (const float*)d_in[1];
    float* out         = (float*)d_out;

    const int rows = in_sizes[0] / FWHT_N;

    fwht4096_kernel<<<rows, FWHT_THREADS>>>(x, scale, out);
}

// round 8
// speedup vs baseline: 1.7703x; 1.7703x over previous
#include <cuda_runtime.h>
#include <cstdint>

// FWHT over rows of length 4096: H4096 = H2^{⊗12}.
// 128 threads/CTA, 32 elements/thread.
// Rounds: A = bits {0,1,9,10,11} (register, from 8 coalesced LDG.128),
//         B = bits {2,3,4}   (float4-granular smem exchange),
//         C = bits {5,6,7,8} (float2-granular smem exchange), then store.
// Swizzle on float4-index F' = F ^ ((F>>3)&7): verified conflict-free for
// all three smem patterns (per 8/16-lane phase) and alignment-preserving.

#define FWHT_N 4096
#define FWHT_THREADS 128

// physical float4 index
__device__ __forceinline__ int swz4(int F) { return F ^ ((F >> 3) & 7); }

__device__ __forceinline__ float4 v4add(float4 a, float4 b) {
    return make_float4(a.x + b.x, a.y + b.y, a.z + b.z, a.w + b.w);
}
__device__ __forceinline__ float4 v4sub(float4 a, float4 b) {
    return make_float4(a.x - b.x, a.y - b.y, a.z - b.z, a.w - b.w);
}

// H8 butterfly across 8 float4 registers (componentwise).
__device__ __forceinline__ void fwht_h8_vec(float4* v) {
#pragma unroll
    for (int h = 1; h < 8; h <<= 1) {
#pragma unroll
        for (int s = 0; s < 8; s += 2 * h) {
#pragma unroll
            for (int k = 0; k < h; k++) {
                float4 a = v[s + k];
                float4 b = v[s + k + h];
                v[s + k]     = v4add(a, b);
                v[s + k + h] = v4sub(a, b);
            }
        }
    }
}

// H4 inside one float4 (element bits {0,1}).
__device__ __forceinline__ float4 fwht_h4_in(float4 a) {
    float x0 = a.x + a.y, x1 = a.x - a.y;
    float x2 = a.z + a.w, x3 = a.z - a.w;
    return make_float4(x0 + x2, x1 + x3, x0 - x2, x1 - x3);
}

__global__ void __launch_bounds__(FWHT_THREADS)
fwht4096_kernel(const float* __restrict__ x,
                const float* __restrict__ scale,
                float* __restrict__ out)
{
    __shared__ float4 S4[FWHT_N / 4];
    float2* S2 = reinterpret_cast<float2*>(S4);

    const int row = blockIdx.x;
    const int t   = threadIdx.x;   // 0..127

    const float4* xr  = reinterpret_cast<const float4*>(x)  + (size_t)row * (FWHT_N / 4);
    float2*       or2 = reinterpret_cast<float2*>(out)      + (size_t)row * (FWHT_N / 2);

    float4 v[8];

    // ---- load: v[j] = x[row, 512j + 4t .. +3]   (8 coalesced LDG.128)
    // elem i = 4t + 512j + k : k->bits{0,1}, t->bits{2..8}, j->bits{9,10,11}
#pragma unroll
    for (int j = 0; j < 8; j++)
        v[j] = __ldcs(&xr[128 * j + t]);

    // ---- round A: H8 across j (bits 9..11) ⊗ H4 in-vector (bits 0,1)
    fwht_h8_vec(v);
#pragma unroll
    for (int j = 0; j < 8; j++)
        v[j] = fwht_h4_in(v[j]);

    // ---- exchange 1: logical float4-idx F = t + 128j
#pragma unroll
    for (int j = 0; j < 8; j++)
        S4[swz4(t + 128 * j)] = v[j];
    __syncthreads();

    // ---- round B: H8 over elem bits {2,3,4}
    // logical F = m | ((t&7)<<3) | ((t>>3)<<6), m = elem bits {2,3,4}
    {
        const int Fb = ((t & 7) << 3) | ((t >> 3) << 6);
#pragma unroll
        for (int m = 0; m < 8; m++)
            v[m] = S4[swz4(Fb | m)];

        fwht_h8_vec(v);   // butterfly across m

#pragma unroll
        for (int m = 0; m < 8; m++)
            S4[swz4(Fb | m)] = v[m];
    }
    __syncthreads();

    // ---- round C: H16 over elem bits {5,6,7,8} at float2 granularity
    // logical float2-idx g = (n<<4) | (t&15) | ((t>>4)<<8), n = elem bits {5..8}
    {
        const int gb = (t & 15) | ((t >> 4) << 8);
        float2 w[16];
#pragma unroll
        for (int n = 0; n < 16; n++) {
            int g = gb | (n << 4);
            w[n] = S2[(swz4(g >> 1) << 1) | (g & 1)];
        }

#pragma unroll
        for (int h = 1; h < 16; h <<= 1) {
#pragma unroll
            for (int s = 0; s < 16; s += 2 * h) {
#pragma unroll
                for (int k = 0; k < h; k++) {
                    float2 a = w[s + k];
                    float2 b = w[s + k + h];
                    w[s + k]     = make_float2(a.x + b.x, a.y + b.y);
                    w[s + k + h] = make_float2(a.x - b.x, a.y - b.y);
                }
            }
        }

        const float sc = *scale;
        // store: global float2-idx g (coalesced 256B per instruction)
#pragma unroll
        for (int n = 0; n < 16; n++) {
            int g = gb | (n << 4);
            float2 a = w[n];
            __stcs(&or2[g], make_float2(a.x * sc, a.y * sc));
        }
    }
}

extern "C" void kernel_launch(void* const* d_in, const int* in_sizes, int n_in,
                              void* d_out, int out_size)
{
    const float* x     = (const float*)d_in[0];
    const float* scale = (const float*)d_in[1];
    float* out         = (float*)d_out;

    const int rows = in_sizes[0] / FWHT_N;

    fwht4096_kernel<<<rows, FWHT_THREADS>>>(x, scale, out);
}

// round 9
// speedup vs baseline: 1.8076x; 1.0211x over previous
#include <cuda_runtime.h>
#include <cstdint>

// FWHT over rows of length 4096: H4096 = H2^{⊗12}.
// 128 threads/CTA, 32 elements/thread.
// Rounds: A = bits {0,1,9,10,11} (register, from 8 coalesced LDG.128),
//         B = bits {2,3,4}   (float4-granular smem exchange),
//         C = bits {5,6,7,8} (float2-granular smem exchange), then store.
// Swizzle on float4-index F' = F ^ ((F>>3)&7): conflict-free for all three
// smem patterns (verified per 8/16-lane phase), alignment-preserving.
// This round: __launch_bounds__(128, 10) to cap regs (~51) and lift
// occupancy 52.7% -> ~62.5% so more warps feed the DRAM read stream.

#define FWHT_N 4096
#define FWHT_THREADS 128

// physical float4 index
__device__ __forceinline__ int swz4(int F) { return F ^ ((F >> 3) & 7); }

__device__ __forceinline__ float4 v4add(float4 a, float4 b) {
    return make_float4(a.x + b.x, a.y + b.y, a.z + b.z, a.w + b.w);
}
__device__ __forceinline__ float4 v4sub(float4 a, float4 b) {
    return make_float4(a.x - b.x, a.y - b.y, a.z - b.z, a.w - b.w);
}

// H8 butterfly across 8 float4 registers (componentwise).
__device__ __forceinline__ void fwht_h8_vec(float4* v) {
#pragma unroll
    for (int h = 1; h < 8; h <<= 1) {
#pragma unroll
        for (int s = 0; s < 8; s += 2 * h) {
#pragma unroll
            for (int k = 0; k < h; k++) {
                float4 a = v[s + k];
                float4 b = v[s + k + h];
                v[s + k]     = v4add(a, b);
                v[s + k + h] = v4sub(a, b);
            }
        }
    }
}

// H4 inside one float4 (element bits {0,1}).
__device__ __forceinline__ float4 fwht_h4_in(float4 a) {
    float x0 = a.x + a.y, x1 = a.x - a.y;
    float x2 = a.z + a.w, x3 = a.z - a.w;
    return make_float4(x0 + x2, x1 + x3, x0 - x2, x1 - x3);
}

__global__ void __launch_bounds__(FWHT_THREADS, 10)
fwht4096_kernel(const float* __restrict__ x,
                const float* __restrict__ scale,
                float* __restrict__ out)
{
    __shared__ float4 S4[FWHT_N / 4];
    float2* S2 = reinterpret_cast<float2*>(S4);

    const int row = blockIdx.x;
    const int t   = threadIdx.x;   // 0..127

    const float4* xr  = reinterpret_cast<const float4*>(x)  + (size_t)row * (FWHT_N / 4);
    float2*       or2 = reinterpret_cast<float2*>(out)      + (size_t)row * (FWHT_N / 2);

    float4 v[8];

    // ---- load: v[j] = x[row, 512j + 4t .. +3]   (8 coalesced LDG.128)
    // elem i = 4t + 512j + k : k->bits{0,1}, t->bits{2..8}, j->bits{9,10,11}
#pragma unroll
    for (int j = 0; j < 8; j++)
        v[j] = __ldcs(&xr[128 * j + t]);

    // ---- round A: H8 across j (bits 9..11) ⊗ H4 in-vector (bits 0,1)
    fwht_h8_vec(v);
#pragma unroll
    for (int j = 0; j < 8; j++)
        v[j] = fwht_h4_in(v[j]);

    // ---- exchange 1: logical float4-idx F = t + 128j
#pragma unroll
    for (int j = 0; j < 8; j++)
        S4[swz4(t + 128 * j)] = v[j];
    __syncthreads();

    // ---- round B: H8 over elem bits {2,3,4}
    // logical F = m | ((t&7)<<3) | ((t>>3)<<6), m = elem bits {2,3,4}
    {
        const int Fb = ((t & 7) << 3) | ((t >> 3) << 6);
#pragma unroll
        for (int m = 0; m < 8; m++)
            v[m] = S4[swz4(Fb | m)];

        fwht_h8_vec(v);   // butterfly across m

#pragma unroll
        for (int m = 0; m < 8; m++)
            S4[swz4(Fb | m)] = v[m];
    }
    __syncthreads();

    // ---- round C: H16 over elem bits {5,6,7,8} at float2 granularity
    // logical float2-idx g = (n<<4) | (t&15) | ((t>>4)<<8), n = elem bits {5..8}
    {
        const int gb = (t & 15) | ((t >> 4) << 8);
        float2 w[16];
#pragma unroll
        for (int n = 0; n < 16; n++) {
            int g = gb | (n << 4);
            w[n] = S2[(swz4(g >> 1) << 1) | (g & 1)];
        }

#pragma unroll
        for (int h = 1; h < 16; h <<= 1) {
#pragma unroll
            for (int s = 0; s < 16; s += 2 * h) {
#pragma unroll
                for (int k = 0; k < h; k++) {
                    float2 a = w[s + k];
                    float2 b = w[s + k + h];
                    w[s + k]     = make_float2(a.x + b.x, a.y + b.y);
                    w[s + k + h] = make_float2(a.x - b.x, a.y - b.y);
                }
            }
        }

        const float sc = *scale;
        // store: global float2-idx g (coalesced 256B per instruction)
#pragma unroll
        for (int n = 0; n < 16; n++) {
            int g = gb | (n << 4);
            float2 a = w[n];
            __stcs(&or2[g], make_float2(a.x * sc, a.y * sc));
        }
    }
}

extern "C" void kernel_launch(void* const* d_in, const int* in_sizes, int n_in,
                              void* d_out, int out_size)
{
    const float* x     = (const float*)d_in[0];
    const float* scale = (const float*)d_in[1];
    float* out         = (float*)d_out;

    const int rows = in_sizes[0] / FWHT_N;

    fwht4096_kernel<<<rows, FWHT_THREADS>>>(x, scale, out);
}